// round 17
// baseline (speedup 1.0000x reference)
#include <cuda_runtime.h>
#include <cuda_fp16.h>
#include <cstdint>
#include <math.h>

// Problem constants
#define NB     16
#define NC     512
#define NHW    1024
#define NHEADS 8
#define ND     64
#define QC     1536     // 3*NC
#define GN_EPS 1e-5f

// ===========================================================================
// Warp-level MMA helpers (sm_80+ paths — legal on base sm_100)
// ===========================================================================
__device__ __forceinline__ uint32_t smem_to_u32(const void* p) {
    uint32_t a;
    asm("{ .reg .u64 t; cvta.to.shared.u64 t, %1; cvt.u32.u64 %0, t; }" : "=r"(a) : "l"(p));
    return a;
}
__device__ __forceinline__ void ldsm4(uint32_t* r, uint32_t addr) {
    asm volatile("ldmatrix.sync.aligned.m8n8.x4.shared.b16 {%0,%1,%2,%3}, [%4];"
                 : "=r"(r[0]), "=r"(r[1]), "=r"(r[2]), "=r"(r[3]) : "r"(addr));
}
__device__ __forceinline__ void ldsm4t(uint32_t* r, uint32_t addr) {
    asm volatile("ldmatrix.sync.aligned.m8n8.x4.trans.shared.b16 {%0,%1,%2,%3}, [%4];"
                 : "=r"(r[0]), "=r"(r[1]), "=r"(r[2]), "=r"(r[3]) : "r"(addr));
}
__device__ __forceinline__ void mma_fp16(float* d, const uint32_t* a, const uint32_t* b) {
    asm volatile("mma.sync.aligned.m16n8k16.row.col.f32.f16.f16.f32 "
                 "{%0,%1,%2,%3}, {%4,%5,%6,%7}, {%8,%9}, {%0,%1,%2,%3};"
                 : "+f"(d[0]), "+f"(d[1]), "+f"(d[2]), "+f"(d[3])
                 : "r"(a[0]), "r"(a[1]), "r"(a[2]), "r"(a[3]), "r"(b[0]), "r"(b[1]));
}
__device__ __forceinline__ void mma4h(float* d, uint32_t a0, uint32_t a1, uint32_t a2,
                                      uint32_t a3, uint32_t b0, uint32_t b1) {
    asm volatile("mma.sync.aligned.m16n8k16.row.col.f32.f16.f16.f32 "
                 "{%0,%1,%2,%3}, {%4,%5,%6,%7}, {%8,%9}, {%0,%1,%2,%3};"
                 : "+f"(d[0]), "+f"(d[1]), "+f"(d[2]), "+f"(d[3])
                 : "r"(a0), "r"(a1), "r"(a2), "r"(a3), "r"(b0), "r"(b1));
}
__device__ __forceinline__ void cp_async16(uint32_t daddr, const void* g) {
    asm volatile("cp.async.cg.shared.global [%0], [%1], 16;" :: "r"(daddr), "l"(g));
}
#define CP_COMMIT() asm volatile("cp.async.commit_group;" ::: "memory")
#define CP_WAIT(N)  asm volatile("cp.async.wait_group %0;" :: "n"(N) : "memory")

// pack two fp32 -> f16x2 (element0 in low half)
__device__ __forceinline__ uint32_t packhf(float lo, float hi) {
    uint32_t r;
    asm("cvt.rn.f16x2.f32 %0, %1, %2;" : "=r"(r) : "f"(hi), "f"(lo));
    return r;
}

// ===========================================================================
// Scratch (device globals — no allocation allowed)
// ===========================================================================
__device__ __half g_xh  [NB * NHW * NC];      // gn out fp16 [b][n][c]
__device__ __half g_ao  [NB * NHW * NC];      // attn out fp16 [b][n][c]
__device__ __half g_qkv [NB * QC * NHW];      // qkv fp16 [b][o][n] (Q pre-scaled)
__device__ __half g_qw  [QC * NC];            // qkv_w fp16 [o][c]
__device__ __half g_pw  [NC * NC];            // proj_w fp16 [o][c]

// ---------------------------------------------------------------------------
// Kernel 1: GroupNorm fused with transpose+fp16 convert.
// ---------------------------------------------------------------------------
__global__ __launch_bounds__(512) void gn_convert(const float* __restrict__ x,
                                                  const float* __restrict__ gw,
                                                  const float* __restrict__ gb,
                                                  __half* __restrict__ dh) {
    int bg = blockIdx.x;
    int b = bg >> 3, g = bg & 7;
    const float* xp = x + (size_t)(b * NC + g * 64) * NHW;
    const int NE4 = 64 * NHW / 4;
    int tid = threadIdx.x;

    float s = 0.f, s2 = 0.f;
    const float4* xp4 = (const float4*)xp;
    for (int i = tid; i < NE4; i += 512) {
        float4 v = xp4[i];
        s  += v.x + v.y + v.z + v.w;
        s2 += v.x * v.x + v.y * v.y + v.z * v.z + v.w * v.w;
    }
    __shared__ float rs[16], rs2[16];
    #pragma unroll
    for (int o = 16; o > 0; o >>= 1) {
        s  += __shfl_down_sync(0xFFFFFFFFu, s, o);
        s2 += __shfl_down_sync(0xFFFFFFFFu, s2, o);
    }
    int w = tid >> 5, l = tid & 31;
    if (l == 0) { rs[w] = s; rs2[w] = s2; }
    __syncthreads();
    __shared__ float sh_mean, sh_rstd;
    if (tid == 0) {
        float S = 0.f, S2 = 0.f;
        #pragma unroll
        for (int i = 0; i < 16; i++) { S += rs[i]; S2 += rs2[i]; }
        float mean = S * (1.f / 65536.f);
        float var  = S2 * (1.f / 65536.f) - mean * mean;
        sh_mean = mean;
        sh_rstd = rsqrtf(var + GN_EPS);
    }
    __syncthreads();
    float mean = sh_mean, rstd = sh_rstd;

    __shared__ float t[64][33];
    int tcol = tid & 31, trow = tid >> 5;
    int n_l  = tid >> 4;
    int cseg = (tid & 15) * 4;
    float sc[4], bi[4];
    #pragma unroll
    for (int i = 0; i < 4; i++) {
        int c = g * 64 + cseg + i;
        sc[i] = gw[c] * rstd;
        bi[i] = gb[c] - mean * sc[i];
    }

    for (int n0 = 0; n0 < NHW; n0 += 32) {
        __syncthreads();
        #pragma unroll
        for (int i = 0; i < 4; i++) {
            int c = trow + i * 16;
            t[c][tcol] = xp[(size_t)c * NHW + n0 + tcol];
        }
        __syncthreads();
        float f0 = t[cseg + 0][n_l] * sc[0] + bi[0];
        float f1 = t[cseg + 1][n_l] * sc[1] + bi[1];
        float f2 = t[cseg + 2][n_l] * sc[2] + bi[2];
        float f3 = t[cseg + 3][n_l] * sc[3] + bi[3];
        uint32_t h0 = packhf(f0, f1), h1 = packhf(f2, f3);
        size_t ob = ((size_t)b * NHW + n0 + n_l) * NC + g * 64 + cseg;
        *(uint2*)(dh + ob) = make_uint2(h0, h1);
    }
}

// ---------------------------------------------------------------------------
// Convert weights fp32 -> fp16
// ---------------------------------------------------------------------------
__global__ void convert_wh(const float* __restrict__ src, __half* __restrict__ dh, int n) {
    int i = blockIdx.x * 256 + threadIdx.x;
    if (i < n) dh[i] = __float2half(src[i]);
}

// ---------------------------------------------------------------------------
// fp16 single-pass GEMM geometry: CTA 128(o) x 64(n), 4 warps (2x2),
// warp 64x32, k-chunk 64, 144B rows, 2-stage, 54KB smem -> 2 CTAs/SM.
// D = W * X, both single fp16.
// ---------------------------------------------------------------------------
#define PJ_ROW    144
#define PJ_A_TILE (128 * PJ_ROW)            // 18432
#define PJ_B_TILE (64 * PJ_ROW)             // 9216
#define PJ_STAGE  (PJ_A_TILE + PJ_B_TILE)   // 27648
#define PJ_SMEM   (2 * PJ_STAGE)            // 55296

#define H1_MAINLOOP()                                                          \
    auto load_stage = [&](int chunk, int s) {                                  \
        int k0 = chunk * 64;                                                   \
        uint32_t sbase = smem_u + s * PJ_STAGE;                                \
        _Pragma("unroll")                                                      \
        for (int t = 0; t < 8; t++) {          /* A: 1024 cp */                \
            int idx = t * 128 + tid;                                           \
            int r = idx >> 3;                                                  \
            int ch = idx & 7;                                                  \
            cp_async16(sbase + r * PJ_ROW + ch * 16,                           \
                       a0 + (size_t)r * NC + k0 + ch * 8);                     \
        }                                                                      \
        _Pragma("unroll")                                                      \
        for (int t = 0; t < 4; t++) {          /* B: 512 cp */                 \
            int idx = t * 128 + tid;                                           \
            int r = idx >> 3;                                                  \
            int ch = idx & 7;                                                  \
            cp_async16(sbase + PJ_A_TILE + r * PJ_ROW + ch * 16,               \
                       b0 + (size_t)r * NC + k0 + ch * 8);                     \
        }                                                                      \
        CP_COMMIT();                                                           \
    };                                                                         \
    float acc[4][4][4] = {};                                                   \
    uint32_t aLane = (uint32_t)((lane & 15) * PJ_ROW + (lane >> 4) * 16);      \
    uint32_t bLane = (uint32_t)(((lane & 7) + ((lane >> 4) << 3)) * PJ_ROW +   \
                                ((lane >> 3) & 1) * 16);                       \
    load_stage(0, 0);                                                          \
    _Pragma("unroll 1")                                                        \
    for (int c = 0; c < 8; c++) {                                              \
        if (c + 1 < 8) { load_stage(c + 1, (c + 1) & 1); CP_WAIT(1); }         \
        else { CP_WAIT(0); }                                                   \
        __syncthreads();                                                       \
        uint32_t sb = smem_u + (c & 1) * PJ_STAGE;                             \
        uint32_t offA = sb + (wm * 64) * PJ_ROW + aLane;                       \
        uint32_t offB = sb + PJ_A_TILE + (wn * 32) * PJ_ROW + bLane;           \
        _Pragma("unroll")                                                      \
        for (int ks = 0; ks < 4; ks++) {                                       \
            uint32_t ko = ks * 32;                                             \
            uint32_t af[4][4], bf[2][4];                                       \
            _Pragma("unroll")                                                  \
            for (int i = 0; i < 4; i++) ldsm4(af[i], offA + i * 16 * PJ_ROW + ko);\
            _Pragma("unroll")                                                  \
            for (int g = 0; g < 2; g++) ldsm4(bf[g], offB + g * 16 * PJ_ROW + ko);\
            _Pragma("unroll")                                                  \
            for (int i = 0; i < 4; i++)                                        \
                _Pragma("unroll")                                              \
                for (int j = 0; j < 4; j++)                                    \
                    mma_fp16(acc[i][j], af[i], &bf[j >> 1][(j & 1) * 2]);      \
        }                                                                      \
        __syncthreads();                                                       \
    }

// QKV: single-pass fp16, writes fp16 in [b][o][n], Q rows scaled by 0.125
__global__ __launch_bounds__(128, 2) void qkv_fp16(
        const __half* __restrict__ W, const __half* __restrict__ X,
        const float* __restrict__ bias, __half* __restrict__ outq) {
    extern __shared__ char smem[];
    uint32_t smem_u = smem_to_u32(smem);
    int tid = threadIdx.x;
    int warp = tid >> 5, lane = tid & 31;
    int wm = warp & 1, wn = warp >> 1;
    int n0 = blockIdx.x * 64;
    int o0 = blockIdx.y * 128;
    int b  = blockIdx.z;

    const __half* a0 = W + (size_t)o0 * NC;
    const __half* b0 = X + ((size_t)b * NHW + n0) * NC;

    H1_MAINLOOP();

    int r0 = lane >> 2, c0 = (lane & 3) * 2;
    #pragma unroll
    for (int i = 0; i < 4; i++) {
        #pragma unroll
        for (int half = 0; half < 2; half++) {
            int o = o0 + wm * 64 + i * 16 + r0 + half * 8;
            float bi = bias[o];
            float scq = (o < NC) ? 0.125f : 1.0f;
            size_t rowb = ((size_t)b * QC + o) * NHW + n0 + wn * 32 + c0;
            #pragma unroll
            for (int j = 0; j < 4; j++) {
                float v0 = (acc[i][j][half * 2]     + bi) * scq;
                float v1 = (acc[i][j][half * 2 + 1] + bi) * scq;
                *(uint32_t*)(outq + rowb + j * 8) = packhf(v0, v1);
            }
        }
    }
}

// Proj: single-pass fp16, fp32 out + bias + residual
__global__ __launch_bounds__(128, 2) void proj_fp16(
        const __half* __restrict__ W, const __half* __restrict__ AO,
        const float* __restrict__ bias, const float* __restrict__ residual,
        float* __restrict__ out) {
    extern __shared__ char smem[];
    uint32_t smem_u = smem_to_u32(smem);
    int tid = threadIdx.x;
    int warp = tid >> 5, lane = tid & 31;
    int wm = warp & 1, wn = warp >> 1;
    int n0 = blockIdx.x * 64;
    int o0 = blockIdx.y * 128;
    int b  = blockIdx.z;

    const __half* a0 = W + (size_t)o0 * NC;
    const __half* b0 = AO + ((size_t)b * NHW + n0) * NC;

    H1_MAINLOOP();

    int r0 = lane >> 2, c0 = (lane & 3) * 2;
    #pragma unroll
    for (int i = 0; i < 4; i++) {
        #pragma unroll
        for (int half = 0; half < 2; half++) {
            int o = o0 + wm * 64 + i * 16 + r0 + half * 8;
            float bi = bias[o];
            size_t rowb = ((size_t)b * NC + o) * NHW + n0 + wn * 32 + c0;
            #pragma unroll
            for (int j = 0; j < 4; j++) {
                float v0 = acc[i][j][half * 2]     + bi;
                float v1 = acc[i][j][half * 2 + 1] + bi;
                size_t off = rowb + j * 8;
                float2 rr = *(const float2*)&residual[off];
                *(float2*)&out[off] = make_float2(v0 + rr.x, v1 + rr.y);
            }
        }
    }
}

// ---------------------------------------------------------------------------
// Flash attention fp16 single: S = Q·K, O = P·V (all single fp16).
// Keeps the R14 pre-O-staging __syncthreads() (O region overlaps KV stages).
// ---------------------------------------------------------------------------
#define QSTR 136
#define KSTR 72
#define OSTR 132
#define Q_BYTES   17408
#define KV_TILE_B 9216
#define STAGE0_OFF Q_BYTES
#define KV_STAGE_B (2 * KV_TILE_B)
#define ATTN_SMEM (STAGE0_OFF + 2 * KV_STAGE_B)   // 54272

__global__ __launch_bounds__(256, 2) void attn_mma() {
    extern __shared__ char smem[];
    uint32_t smem_u = smem_to_u32(smem);
    int tid  = threadIdx.x;
    int warp = tid >> 5, lane = tid & 31;
    int wbase = warp * 16;
    int qt = blockIdx.x, h = blockIdx.y, b = blockIdx.z;

    const __half* gq = g_qkv + ((size_t)b * QC + h * ND) * NHW;
    const __half* gk = g_qkv + ((size_t)b * QC + NC + h * ND) * NHW;
    const __half* gv = g_qkv + ((size_t)b * QC + 2 * NC + h * ND) * NHW;
    const __half* kvsrc[2] = {gk, gv};

    int rowoff = ((lane >> 4) << 3) + (lane & 7);
    int coloff = ((lane >> 3) & 1) * 8;

    auto load_stage = [&](int kt, int s) {
        uint32_t sb = smem_u + STAGE0_OFF + s * KV_STAGE_B;
        #pragma unroll
        for (int k = 0; k < 4; k++) {
            int c = tid + k * 256;
            int tile = c >> 9, row = (c >> 3) & 63, ch = c & 7;
            cp_async16(sb + tile * KV_TILE_B + row * (KSTR * 2) + ch * 16,
                       kvsrc[tile] + (size_t)row * NHW + kt * 64 + ch * 8);
        }
        CP_COMMIT();
    };

    // preload Q (single tile, 1024 cp)
    {
        #pragma unroll
        for (int k = 0; k < 4; k++) {
            int c = tid + k * 256;
            int row = (c >> 4) & 63, ch = c & 15;
            cp_async16(smem_u + row * (QSTR * 2) + ch * 16,
                       gq + (size_t)row * NHW + qt * 128 + ch * 8);
        }
    }
    load_stage(0, 0);

    float m0 = -1e30f, m1 = -1e30f, l0 = 0.f, l1 = 0.f;
    float oacc[8][4] = {};

    uint32_t qAddr = smem_u + (uint32_t)(rowoff * (QSTR * 2) + (wbase + coloff) * 2);

    #pragma unroll 1
    for (int kt = 0; kt < 16; kt++) {
        CP_WAIT(0);
        __syncthreads();
        if (kt < 15) load_stage(kt + 1, (kt + 1) & 1);

        uint32_t sb = smem_u + STAGE0_OFF + (kt & 1) * KV_STAGE_B;
        float sacc[8][4] = {};
        #pragma unroll
        for (int kc = 0; kc < 4; kc++) {
            uint32_t qh[4];
            ldsm4t(qh, qAddr + kc * 16 * (QSTR * 2));
            uint32_t kBase = sb + (uint32_t)((kc * 16 + rowoff) * (KSTR * 2) + coloff * 2);
            #pragma unroll
            for (int ko2 = 0; ko2 < 4; ko2++) {
                uint32_t kh[4];
                ldsm4t(kh, kBase + ko2 * 32);
                mma4h(sacc[2*ko2],   qh[0],qh[1],qh[2],qh[3], kh[0], kh[2]);
                mma4h(sacc[2*ko2+1], qh[0],qh[1],qh[2],qh[3], kh[1], kh[3]);
            }
        }

        float tm0 = -1e30f, tm1 = -1e30f;
        #pragma unroll
        for (int j = 0; j < 8; j++) {
            tm0 = fmaxf(tm0, fmaxf(sacc[j][0], sacc[j][1]));
            tm1 = fmaxf(tm1, fmaxf(sacc[j][2], sacc[j][3]));
        }
        tm0 = fmaxf(tm0, __shfl_xor_sync(0xFFFFFFFFu, tm0, 1));
        tm0 = fmaxf(tm0, __shfl_xor_sync(0xFFFFFFFFu, tm0, 2));
        tm1 = fmaxf(tm1, __shfl_xor_sync(0xFFFFFFFFu, tm1, 1));
        tm1 = fmaxf(tm1, __shfl_xor_sync(0xFFFFFFFFu, tm1, 2));
        float nm0 = fmaxf(m0, tm0), nm1 = fmaxf(m1, tm1);
        float al0 = __expf(m0 - nm0), al1 = __expf(m1 - nm1);
        m0 = nm0; m1 = nm1;
        float sum0 = 0.f, sum1 = 0.f;
        #pragma unroll
        for (int j = 0; j < 8; j++) {
            sacc[j][0] = __expf(sacc[j][0] - m0); sum0 += sacc[j][0];
            sacc[j][1] = __expf(sacc[j][1] - m0); sum0 += sacc[j][1];
            sacc[j][2] = __expf(sacc[j][2] - m1); sum1 += sacc[j][2];
            sacc[j][3] = __expf(sacc[j][3] - m1); sum1 += sacc[j][3];
        }
        sum0 += __shfl_xor_sync(0xFFFFFFFFu, sum0, 1);
        sum0 += __shfl_xor_sync(0xFFFFFFFFu, sum0, 2);
        sum1 += __shfl_xor_sync(0xFFFFFFFFu, sum1, 1);
        sum1 += __shfl_xor_sync(0xFFFFFFFFu, sum1, 2);
        l0 = l0 * al0 + sum0;
        l1 = l1 * al1 + sum1;
        #pragma unroll
        for (int d = 0; d < 8; d++) {
            oacc[d][0] *= al0; oacc[d][1] *= al0;
            oacc[d][2] *= al1; oacc[d][3] *= al1;
        }

        uint32_t vB = sb + KV_TILE_B;
        #pragma unroll
        for (int kc2 = 0; kc2 < 4; kc2++) {
            int j0 = 2 * kc2, j1 = j0 + 1;
            uint32_t pa0 = packhf(sacc[j0][0], sacc[j0][1]);
            uint32_t pa1 = packhf(sacc[j0][2], sacc[j0][3]);
            uint32_t pa2 = packhf(sacc[j1][0], sacc[j1][1]);
            uint32_t pa3 = packhf(sacc[j1][2], sacc[j1][3]);
            uint32_t vCol = (uint32_t)((kc2 * 16 + coloff) * 2);
            #pragma unroll
            for (int do2 = 0; do2 < 4; do2++) {
                uint32_t vh[4];
                uint32_t vRow = (uint32_t)((do2 * 16 + rowoff) * (KSTR * 2));
                ldsm4(vh, vB + vRow + vCol);
                mma4h(oacc[2*do2],   pa0,pa1,pa2,pa3, vh[0], vh[1]);
                mma4h(oacc[2*do2+1], pa0,pa1,pa2,pa3, vh[2], vh[3]);
            }
        }
    }

    // All warps must retire their last PV ldsm/mma before O-staging
    // overwrites the KV stage regions (Os overlaps both stages).
    __syncthreads();

    float* Os = (float*)(smem + STAGE0_OFF);
    float linv0 = 1.f / l0, linv1 = 1.f / l1;
    int r0q = wbase + (lane >> 2);
    int ddc = (lane & 3) * 2;
    #pragma unroll
    for (int d = 0; d < 8; d++) {
        Os[(d * 8 + ddc)     * OSTR + r0q]     = oacc[d][0] * linv0;
        Os[(d * 8 + ddc + 1) * OSTR + r0q]     = oacc[d][1] * linv0;
        Os[(d * 8 + ddc)     * OSTR + r0q + 8] = oacc[d][2] * linv1;
        Os[(d * 8 + ddc + 1) * OSTR + r0q + 8] = oacc[d][3] * linv1;
    }
    __syncthreads();

    // coop write: fp16 ao to [b][n][c]
    {
        int q = tid >> 1;
        int ddb = (tid & 1) * 32;
        uint32_t hb[16];
        #pragma unroll
        for (int d = 0; d < 32; d += 2) {
            float f0 = Os[(ddb + d)     * OSTR + q];
            float f1 = Os[(ddb + d + 1) * OSTR + q];
            hb[d >> 1] = packhf(f0, f1);
        }
        size_t base = ((size_t)b * NHW + qt * 128 + q) * NC + h * 64 + ddb;
        #pragma unroll
        for (int u = 0; u < 4; u++)
            *(uint4*)(g_ao + base + u * 8) = *(uint4*)&hb[u * 4];
    }
}

// ---------------------------------------------------------------------------
extern "C" void kernel_launch(void* const* d_in, const int* in_sizes, int n_in,
                              void* d_out, int out_size) {
    const float* x      = (const float*)d_in[0];
    const float* gn_w   = (const float*)d_in[1];
    const float* gn_b   = (const float*)d_in[2];
    const float* qkv_w  = (const float*)d_in[3];
    const float* qkv_b  = (const float*)d_in[4];
    const float* proj_w = (const float*)d_in[5];
    const float* proj_b = (const float*)d_in[6];
    float* out = (float*)d_out;

    cudaFuncSetAttribute(qkv_fp16, cudaFuncAttributeMaxDynamicSharedMemorySize, PJ_SMEM);
    cudaFuncSetAttribute(proj_fp16, cudaFuncAttributeMaxDynamicSharedMemorySize, PJ_SMEM);
    cudaFuncSetAttribute(attn_mma, cudaFuncAttributeMaxDynamicSharedMemorySize, ATTN_SMEM);

    __half *qw, *pw, *xh, *ao, *qkv;
    cudaGetSymbolAddress((void**)&qw, g_qw);
    cudaGetSymbolAddress((void**)&pw, g_pw);
    cudaGetSymbolAddress((void**)&xh, g_xh);
    cudaGetSymbolAddress((void**)&ao, g_ao);
    cudaGetSymbolAddress((void**)&qkv, g_qkv);

    // 1. GroupNorm fused with transpose+fp16 convert -> g_xh [b][n][c]
    gn_convert<<<NB * 8, 512>>>(x, gn_w, gn_b, xh);
    // 2. Weight conversion (fp16)
    convert_wh<<<(QC * NC + 255) / 256, 256>>>(qkv_w, qw, QC * NC);
    convert_wh<<<(NC * NC + 255) / 256, 256>>>(proj_w, pw, NC * NC);
    // 3. QKV GEMM fp16 single-pass, writes fp16 (Q scaled)
    qkv_fp16<<<dim3(NHW / 64, QC / 128, NB), 128, PJ_SMEM>>>(
        qw, xh, qkv_b, qkv);
    // 4. Flash attention fp16 single
    attn_mma<<<dim3(NHW / 128, NHEADS, NB), 256, ATTN_SMEM>>>();
    // 5. Proj GEMM fp16 single-pass + bias + residual
    proj_fp16<<<dim3(NHW / 64, NC / 128, NB), 128, PJ_SMEM>>>(
        pw, ao, proj_b, x, out);
}